// round 16
// baseline (speedup 1.0000x reference)
#include <cuda_runtime.h>
#include <cuda_fp16.h>
#include <math.h>
#include <stdint.h>

#define S_LEN   2048
#define D_MODEL 1024
#define NH      16
#define DH      64
#define BATCH   2
#define M_ROWS  (BATCH * S_LEN)   // 4096

// ---------------------------------------------------------------------------
// Scratch (device globals: allocation-free, graph-capture safe)
// ---------------------------------------------------------------------------
__device__ __half g_qh[M_ROWS * D_MODEL];
__device__ __half g_kh[M_ROWS * D_MODEL];
__device__ __half g_vh[M_ROWS * D_MODEL];
__device__ __half g_atth[M_ROWS * D_MODEL];
__device__ __half g_xh[M_ROWS * D_MODEL];
__device__ __half g_wh[4][D_MODEL * D_MODEL];

// ---------------------------------------------------------------------------
// Helpers
// ---------------------------------------------------------------------------
__device__ __forceinline__ void mma_f16(float* c, const uint32_t* a,
                                        const uint32_t* b) {
    asm volatile(
        "mma.sync.aligned.m16n8k16.row.col.f32.f16.f16.f32 "
        "{%0,%1,%2,%3}, {%4,%5,%6,%7}, {%8,%9}, {%0,%1,%2,%3};\n"
        : "+f"(c[0]), "+f"(c[1]), "+f"(c[2]), "+f"(c[3])
        : "r"(a[0]), "r"(a[1]), "r"(a[2]), "r"(a[3]),
          "r"(b[0]), "r"(b[1]));
}

#define LDSM_X4(r0, r1, r2, r3, addr) \
    asm volatile("ldmatrix.sync.aligned.m8n8.x4.shared.b16 {%0,%1,%2,%3}, [%4];" \
                 : "=r"(r0), "=r"(r1), "=r"(r2), "=r"(r3) : "r"(addr))

#define LDSM_X4_T(r0, r1, r2, r3, addr) \
    asm volatile("ldmatrix.sync.aligned.m8n8.x4.trans.shared.b16 {%0,%1,%2,%3}, [%4];" \
                 : "=r"(r0), "=r"(r1), "=r"(r2), "=r"(r3) : "r"(addr))

#define LDSM_X2_T(r0, r1, addr) \
    asm volatile("ldmatrix.sync.aligned.m8n8.x2.trans.shared.b16 {%0,%1}, [%2];" \
                 : "=r"(r0), "=r"(r1) : "r"(addr))

__device__ __forceinline__ uint32_t smemu32(const void* p) {
    return (uint32_t)__cvta_generic_to_shared(p);
}

// Pack two fp32 into fp16x2 (RNE), lo = a, hi = b
__device__ __forceinline__ uint32_t pack_h2(float a, float b) {
    uint32_t r;
    asm("cvt.rn.f16x2.f32 %0, %1, %2;" : "=r"(r) : "f"(b), "f"(a));
    return r;
}

// exp2 approximations (MUFU)
__device__ __forceinline__ uint32_t hex2(uint32_t x) {
    uint32_t r;
    asm("ex2.approx.f16x2 %0, %1;" : "=r"(r) : "r"(x));
    return r;
}
__device__ __forceinline__ float fex2(float x) {
    float r;
    asm("ex2.approx.f32 %0, %1;" : "=f"(r) : "f"(x));
    return r;
}

#define CP_ASYNC16(dst, src) \
    asm volatile("cp.async.cg.shared.global [%0], [%1], 16;\n" \
                 :: "r"(dst), "l"(src))
#define CP_COMMIT() asm volatile("cp.async.commit_group;\n" ::: "memory")

// ---------------------------------------------------------------------------
// Fused fp32 -> fp16 prep: grid.y selects tensor (0=X, 1..4=W)
// ---------------------------------------------------------------------------
#define NX8 (M_ROWS * D_MODEL / 8)
#define NW8 (D_MODEL * D_MODEL / 8)

__global__ void f2h5_kernel(const float* __restrict__ x,
                            const float* __restrict__ wq,
                            const float* __restrict__ wk,
                            const float* __restrict__ wv,
                            const float* __restrict__ wo,
                            __half* __restrict__ xh,
                            __half* __restrict__ wh)
{
    const int z = blockIdx.y;
    const int i = blockIdx.x * blockDim.x + threadIdx.x;
    const float* src;
    __half* dst;
    int n8;
    if (z == 0) { src = x; dst = xh; n8 = NX8; }
    else {
        src = (z == 1) ? wq : (z == 2) ? wk : (z == 3) ? wv : wo;
        dst = wh + (size_t)(z - 1) * D_MODEL * D_MODEL;
        n8 = NW8;
    }
    if (i < n8) {
        float4 v0 = ((const float4*)src)[i * 2];
        float4 v1 = ((const float4*)src)[i * 2 + 1];
        uint4 u;
        u.x = pack_h2(v0.x, v0.y);
        u.y = pack_h2(v0.z, v0.w);
        u.z = pack_h2(v1.x, v1.y);
        u.w = pack_h2(v1.z, v1.w);
        ((uint4*)dst)[i] = u;
    }
}

// ---------------------------------------------------------------------------
// FP16 tensor-core GEMM: Y[M,N] = X[M,K] @ W[N,K]^T  (fp32 accumulate)
// R9/R13 tile config: BM=BN=128, BK=32, 256 threads (8 warps, 2x4), warp
// tile 64x32; 3-stage cp.async ring, one sync/iter.
// NEW: __launch_bounds__(256, 3) — cap regs at 85 so 3 CTAs/SM fit (24
// warps/SM, +50% latency hiding; smem 61.4KB x 3 = 184KB fits).
// ---------------------------------------------------------------------------
#define HST 20                        // smem row stride in 4B words
#define HSTAGE_W (128 * HST)          // words per operand per stage
#define HSMEM_BYTES (6 * HSTAGE_W * 4)   // 3 stages x 2 operands = 61440 B

template <typename OT>
__global__ __launch_bounds__(256, 3) void gemm_h(
    const __half* __restrict__ X,
    const __half* __restrict__ W0, const __half* __restrict__ W1,
    const __half* __restrict__ W2,
    OT* __restrict__ Y0, OT* __restrict__ Y1, OT* __restrict__ Y2,
    int M, int N, int K)
{
    extern __shared__ __align__(16) uint32_t gsm[];

    const int z = blockIdx.z;
    const __half* W = (z == 0) ? W0 : (z == 1) ? W1 : W2;
    OT*           Y = (z == 0) ? Y0 : (z == 1) ? Y1 : Y2;

    const int tid  = threadIdx.x;
    const int lane = tid & 31;
    const int warp = tid >> 5;
    const int wm   = warp >> 2;       // 0..1
    const int wn   = warp & 3;        // 0..3
    const int grp  = lane >> 2;       // 0..7
    const int t4   = lane & 3;        // 0..3

    const int row0 = blockIdx.y * 128;
    const int col0 = blockIdx.x * 128;

    // cp.async mapping: thread covers one 16-half chunk per operand
    const int lr = tid >> 1;          // 0..127
    const int lh = (tid & 1) * 16;    // 0 or 16 halfs
    const __half* Xg = X + (size_t)(row0 + lr) * K + lh;
    const __half* Wg = W + (size_t)(col0 + lr) * K + lh;
    const uint32_t sbase = smemu32(gsm);
    const uint32_t doff  = (uint32_t)(lr * HST + (tid & 1) * 8) * 4u;

    auto issue_stage = [&](int it) {
        const int s  = it % 3;
        const int k0 = it * 32;
        uint32_t xd = sbase + (uint32_t)(s * 2)     * HSTAGE_W * 4u + doff;
        uint32_t wd = sbase + (uint32_t)(s * 2 + 1) * HSTAGE_W * 4u + doff;
        CP_ASYNC16(xd,      Xg + k0);
        CP_ASYNC16(xd + 16, Xg + k0 + 8);
        CP_ASYNC16(wd,      Wg + k0);
        CP_ASYNC16(wd + 16, Wg + k0 + 8);
        CP_COMMIT();
    };

    // ldmatrix lane offsets (bytes)
    const uint32_t aoff = (uint32_t)((wm * 64 + (lane & 15)) * HST * 4
                                     + ((lane >> 4) & 1) * 16);
    const uint32_t boff = (uint32_t)((wn * 32 + (lane & 7) + ((lane >> 4) << 3))
                                     * HST * 4 + ((lane >> 3) & 1) * 16);

    float acc[4][4][4] = {};

    const int niter = K / 32;         // 32
    issue_stage(0);
    issue_stage(1);

    for (int it = 0; it < niter; it++) {
        if (it + 1 < niter)
            asm volatile("cp.async.wait_group 1;" ::: "memory");
        else
            asm volatile("cp.async.wait_group 0;" ::: "memory");
        __syncthreads();
        if (it + 2 < niter) issue_stage(it + 2);   // safe: 3-stage ring

        const uint32_t xsb = sbase + (uint32_t)((it % 3) * 2) * HSTAGE_W * 4u;
        const uint32_t wsb = xsb + HSTAGE_W * 4u;

        #pragma unroll
        for (int ks = 0; ks < 2; ks++) {
            const uint32_t kb = ks * 32;   // 8 words = 16 halfs
            uint32_t a[4][4], b[2][4];
            #pragma unroll
            for (int am = 0; am < 4; am++)
                LDSM_X4(a[am][0], a[am][1], a[am][2], a[am][3],
                        xsb + aoff + (uint32_t)(am * 16 * HST * 4) + kb);
            #pragma unroll
            for (int bp = 0; bp < 2; bp++)
                LDSM_X4(b[bp][0], b[bp][1], b[bp][2], b[bp][3],
                        wsb + boff + (uint32_t)(bp * 16 * HST * 4) + kb);
            #pragma unroll
            for (int am = 0; am < 4; am++)
                #pragma unroll
                for (int bn = 0; bn < 4; bn++)
                    mma_f16(acc[am][bn], a[am], &b[bn >> 1][(bn & 1) * 2]);
        }
    }

    #pragma unroll
    for (int am = 0; am < 4; am++) {
        const int r = row0 + wm * 64 + am * 16 + grp;
        #pragma unroll
        for (int bn = 0; bn < 4; bn++) {
            const int c = col0 + wn * 32 + bn * 8 + t4 * 2;
            if (sizeof(OT) == 4) {
                *(float2*)((float*)Y + (size_t)r * N + c) =
                    make_float2(acc[am][bn][0], acc[am][bn][1]);
                *(float2*)((float*)Y + (size_t)(r + 8) * N + c) =
                    make_float2(acc[am][bn][2], acc[am][bn][3]);
            } else {
                *(uint32_t*)((__half*)Y + (size_t)r * N + c) =
                    pack_h2(acc[am][bn][0], acc[am][bn][1]);
                *(uint32_t*)((__half*)Y + (size_t)(r + 8) * N + c) =
                    pack_h2(acc[am][bn][2], acc[am][bn][3]);
            }
        }
    }
}

// ---------------------------------------------------------------------------
// FP16 flash attention (causal), log2-domain softmax, l via tensor core
// (R13 config, proven 280.6us total).  NEW: __launch_bounds__(256, 3) for
// 3 CTAs/SM (smem 73.7KB x 3 = 221KB fits; regs capped at 85).
// BQ=128, BKV=64, 256 threads (8 warps); warp w owns q-rows [16w, 16w+16).
// ---------------------------------------------------------------------------
#define FST 36   // word stride (ldmatrix conflict-free: banks 4r)
#define KVSTAGE_W (128 * FST)                    // K 64 rows + V 64 rows
#define ATTN_SMEM_BYTES ((128 * FST + 3 * KVSTAGE_W) * 4)   // 73728 B
#define SCALE_L2E 0.1803368801111244f            // 0.125 * log2(e)

__global__ __launch_bounds__(256, 3) void attn_h(
    const __half* __restrict__ Qg, const __half* __restrict__ Kg,
    const __half* __restrict__ Vg, __half* __restrict__ Og)
{
    extern __shared__ __align__(16) uint32_t sm[];
    uint32_t* Qs = sm;                  // [128][32w] (i, d)

    const int tid  = threadIdx.x;
    const int lane = tid & 31;
    const int warp = tid >> 5;
    const int grp  = lane >> 2;         // 0..7
    const int t4   = lane & 3;          // 0..3
    const int m0   = warp * 16;

    const int qt = (gridDim.x - 1) - blockIdx.x;   // heavy tiles first
    const int q0 = qt * 128;
    const int h  = blockIdx.y;
    const int b  = blockIdx.z;

    const __half* Qb = Qg + ((size_t)b * S_LEN + q0) * D_MODEL + h * DH;
    const __half* Kb = Kg + (size_t)b * S_LEN * D_MODEL + h * DH;
    const __half* Vb = Vg + (size_t)b * S_LEN * D_MODEL + h * DH;

    const uint32_t sQ  = smemu32(Qs);
    const uint32_t sKV = sQ + 128 * FST * 4;

    // ldmatrix lane offsets (bytes)
    const uint32_t aoff = (uint32_t)((lane & 15) * FST * 4
                                     + ((lane >> 4) & 1) * 16);
    const uint32_t boff = (uint32_t)(((lane & 7) + ((lane >> 4) << 3)) * FST * 4
                                     + ((lane >> 3) & 1) * 16);
    // trans B-operand offsets for V (rows = j, 16B col select by lane>>4)
    const uint32_t voff = (uint32_t)((lane & 15) * FST * 4
                                     + ((lane >> 4) & 1) * 16);
    // ones-column (col 64) B-operand offset: 16 rows, bytes 128..143
    const uint32_t loff = (uint32_t)((lane & 15) * FST * 4 + 128);

    // cp.async mapping for K/V tiles: 2 chunks each per thread
    const int krow = tid >> 3;          // 0..31 base (2 rounds -> 64 rows)
    const int kch  = tid & 7;           // 16B chunk in row

    auto issue_kv = [&](int kt) {
        const int s  = kt % 3;
        const int k0 = kt * 64;
        const uint32_t base = sKV + (uint32_t)s * KVSTAGE_W * 4u;
        #pragma unroll
        for (int r = 0; r < 2; r++) {
            const int row = krow + r * 32;
            const uint32_t d = base + (uint32_t)(row * FST * 4 + kch * 16);
            CP_ASYNC16(d, Kb + (size_t)(k0 + row) * D_MODEL + kch * 8);
            CP_ASYNC16(d + (uint32_t)(64 * FST * 4),
                       Vb + (size_t)(k0 + row) * D_MODEL + kch * 8);
        }
        CP_COMMIT();
    };

    issue_kv(0);

    // Init ones-column words (32..35) of every V row, all 3 ring stages.
    // cp.async never touches these words; the in-loop __syncthreads covers
    // visibility before first use.
    for (int i = tid; i < 3 * 64; i += 256) {
        const int st = i >> 6, row = i & 63;
        uint32_t* p = sm + 128 * FST + st * KVSTAGE_W + 64 * FST + row * FST + 32;
        p[0] = 0x00003C00u;   // col 64 = 1.0h, col 65 = 0
        p[1] = 0; p[2] = 0; p[3] = 0;
    }

    // Load Q tile (128 x 64 halfs)
    #pragma unroll
    for (int r = 0; r < 4; r++) {
        int idx = tid + r * 256;
        int row = idx >> 3;             // 0..127
        int ch  = idx & 7;              // 8 halfs each
        uint4 v = *(const uint4*)(Qb + (size_t)row * D_MODEL + ch * 8);
        *(uint4*)(Qs + row * FST + ch * 4) = v;
    }

    float mr[2] = {-INFINITY, -INFINITY};
    float o[8][4];
    float l_acc[4] = {0.f, 0.f, 0.f, 0.f};
    #pragma unroll
    for (int n = 0; n < 8; n++)
        #pragma unroll
        for (int r = 0; r < 4; r++) o[n][r] = 0.f;

    const int ntiles = 2 * qt + 2;
    if (ntiles > 1) issue_kv(1);

    for (int kt = 0; kt < ntiles; kt++) {
        if (kt + 1 < ntiles)
            asm volatile("cp.async.wait_group 1;" ::: "memory");
        else
            asm volatile("cp.async.wait_group 0;" ::: "memory");
        __syncthreads();
        if (kt + 2 < ntiles) issue_kv(kt + 2);   // safe: 3-stage ring

        const int k0 = kt * 64;
        const uint32_t sKst = sKV + (uint32_t)((kt % 3)) * KVSTAGE_W * 4u;
        const uint32_t sVst = sKst + (uint32_t)(64 * FST * 4);

        const bool active = (k0 <= q0 + m0 + 15);
        if (active) {
            // ---- S = Q K^T ----
            float s[8][4];
            #pragma unroll
            for (int n = 0; n < 8; n++)
                #pragma unroll
                for (int r = 0; r < 4; r++) s[n][r] = 0.f;

            #pragma unroll
            for (int ks = 0; ks < 4; ks++) {
                const uint32_t kb = ks * 32;
                uint32_t a[4], bk[4][4];
                LDSM_X4(a[0], a[1], a[2], a[3],
                        sQ + (uint32_t)(m0 * FST * 4) + aoff + kb);
                #pragma unroll
                for (int np = 0; np < 4; np++)
                    LDSM_X4(bk[np][0], bk[np][1], bk[np][2], bk[np][3],
                            sKst + boff + (uint32_t)(np * 16 * FST * 4) + kb);
                #pragma unroll
                for (int n = 0; n < 8; n++)
                    mma_f16(s[n], a, &bk[n >> 1][(n & 1) * 2]);
            }
            // scale into log2 domain: s * 0.125 * log2(e)
            #pragma unroll
            for (int n = 0; n < 8; n++) {
                s[n][0] *= SCALE_L2E; s[n][1] *= SCALE_L2E;
                s[n][2] *= SCALE_L2E; s[n][3] *= SCALE_L2E;
            }

            // ---- causal mask (only when tile clips this warp's rows) ----
            if (k0 + 63 > q0 + m0) {
                const int i0 = q0 + m0 + grp, i1 = i0 + 8;
                #pragma unroll
                for (int n = 0; n < 8; n++) {
                    const int j0 = k0 + n * 8 + t4 * 2;
                    if (j0     > i0) s[n][0] = -INFINITY;
                    if (j0 + 1 > i0) s[n][1] = -INFINITY;
                    if (j0     > i1) s[n][2] = -INFINITY;
                    if (j0 + 1 > i1) s[n][3] = -INFINITY;
                }
            }

            // ---- online softmax max (rows grp, grp+8; quad shuffles) ----
            float ml0 = -INFINITY, ml1 = -INFINITY;
            #pragma unroll
            for (int n = 0; n < 8; n++) {
                ml0 = fmaxf(ml0, fmaxf(s[n][0], s[n][1]));
                ml1 = fmaxf(ml1, fmaxf(s[n][2], s[n][3]));
            }
            ml0 = fmaxf(ml0, __shfl_xor_sync(0xffffffffu, ml0, 1));
            ml0 = fmaxf(ml0, __shfl_xor_sync(0xffffffffu, ml0, 2));
            ml1 = fmaxf(ml1, __shfl_xor_sync(0xffffffffu, ml1, 1));
            ml1 = fmaxf(ml1, __shfl_xor_sync(0xffffffffu, ml1, 2));

            const float mn0 = fmaxf(mr[0], ml0);
            const float mn1 = fmaxf(mr[1], ml1);
            const float al0 = fex2(mr[0] - mn0);
            const float al1 = fex2(mr[1] - mn1);
            mr[0] = mn0; mr[1] = mn1;

            // ---- P = exp2(s - m) directly in fp16x2 (A-fragment layout) ----
            uint32_t p2[8][2];
            #pragma unroll
            for (int n = 0; n < 8; n++) {
                p2[n][0] = hex2(pack_h2(s[n][0] - mn0, s[n][1] - mn0));
                p2[n][1] = hex2(pack_h2(s[n][2] - mn1, s[n][3] - mn1));
            }

            // rescale O and l by alpha
            #pragma unroll
            for (int n = 0; n < 8; n++) {
                o[n][0] *= al0; o[n][1] *= al0;
                o[n][2] *= al1; o[n][3] *= al1;
            }
            l_acc[0] *= al0; l_acc[1] *= al0;
            l_acc[2] *= al1; l_acc[3] *= al1;

            // ---- O += P V, l += P 1 (ones column) ----
            #pragma unroll
            for (int ks = 0; ks < 4; ks++) {
                uint32_t ap[4], bv[4][4], bl[2];
                ap[0] = p2[2 * ks][0];
                ap[1] = p2[2 * ks][1];
                ap[2] = p2[2 * ks + 1][0];
                ap[3] = p2[2 * ks + 1][1];
                const uint32_t vrow = sVst + (uint32_t)(ks * 16 * FST * 4);
                #pragma unroll
                for (int np = 0; np < 4; np++)
                    LDSM_X4_T(bv[np][0], bv[np][1], bv[np][2], bv[np][3],
                              vrow + voff + (uint32_t)(np * 32));
                LDSM_X2_T(bl[0], bl[1], vrow + loff);
                #pragma unroll
                for (int n = 0; n < 8; n++)
                    mma_f16(o[n], ap, &bv[n >> 1][(n & 1) * 2]);
                mma_f16(l_acc, ap, bl);
            }
        }
    }

    // ---- broadcast row sums (col 0 of l fragment lives at t4==0) ----
    const float l0 = __shfl_sync(0xffffffffu, l_acc[0], lane & ~3);
    const float l1 = __shfl_sync(0xffffffffu, l_acc[2], lane & ~3);
    const float inv0 = 1.f / l0;
    const float inv1 = 1.f / l1;

    __half* Ob = Og + ((size_t)b * S_LEN + q0 + m0) * D_MODEL + h * DH;
    #pragma unroll
    for (int n = 0; n < 8; n++) {
        const int c = n * 8 + t4 * 2;
        *(uint32_t*)(Ob + (size_t)grp * D_MODEL + c) =
            pack_h2(o[n][0] * inv0, o[n][1] * inv0);
        *(uint32_t*)(Ob + (size_t)(grp + 8) * D_MODEL + c) =
            pack_h2(o[n][2] * inv1, o[n][3] * inv1);
    }
}

// ---------------------------------------------------------------------------
// Launch
// ---------------------------------------------------------------------------
extern "C" void kernel_launch(void* const* d_in, const int* in_sizes, int n_in,
                              void* d_out, int out_size)
{
    const float* x  = (const float*)d_in[0];
    const float* Wq = (const float*)d_in[1];
    const float* Wk = (const float*)d_in[2];
    const float* Wv = (const float*)d_in[3];
    const float* Wo = (const float*)d_in[4];
    float* out = (float*)d_out;

    __half *q, *k, *v, *att, *xh, *wh;
    cudaGetSymbolAddress((void**)&q,   g_qh);
    cudaGetSymbolAddress((void**)&k,   g_kh);
    cudaGetSymbolAddress((void**)&v,   g_vh);
    cudaGetSymbolAddress((void**)&att, g_atth);
    cudaGetSymbolAddress((void**)&xh,  g_xh);
    cudaGetSymbolAddress((void**)&wh,  g_wh);
    __half* wq = wh;
    __half* wk = wh + 1 * (size_t)D_MODEL * D_MODEL;
    __half* wv = wh + 2 * (size_t)D_MODEL * D_MODEL;
    __half* wo = wh + 3 * (size_t)D_MODEL * D_MODEL;

    cudaFuncSetAttribute(gemm_h<__half>,
                         cudaFuncAttributeMaxDynamicSharedMemorySize, HSMEM_BYTES);
    cudaFuncSetAttribute(gemm_h<float>,
                         cudaFuncAttributeMaxDynamicSharedMemorySize, HSMEM_BYTES);
    cudaFuncSetAttribute(attn_h,
                         cudaFuncAttributeMaxDynamicSharedMemorySize, ATTN_SMEM_BYTES);

    // fp32 -> fp16 prep, one launch (grid.y selects tensor)
    f2h5_kernel<<<dim3(NX8 / 256, 5), 256>>>(x, Wq, Wk, Wv, Wo, xh, wh);

    // Fused QKV projections (fp16 out)
    dim3 gq(D_MODEL / 128, M_ROWS / 128, 3);   // (8, 32, 3)
    gemm_h<__half><<<gq, 256, HSMEM_BYTES>>>(xh, wq, wk, wv, q, k, v,
                                             M_ROWS, D_MODEL, D_MODEL);

    attn_h<<<dim3(S_LEN / 128, NH, BATCH), 256, ATTN_SMEM_BYTES>>>(q, k, v, att);

    // O projection (fp32 out to d_out)
    dim3 go(D_MODEL / 128, M_ROWS / 128, 1);
    gemm_h<float><<<go, 256, HSMEM_BYTES>>>(att, wo, wo, wo, out, out, out,
                                            M_ROWS, D_MODEL, D_MODEL);
}

// round 17
// speedup vs baseline: 1.3542x; 1.3542x over previous
#include <cuda_runtime.h>
#include <cuda_fp16.h>
#include <math.h>
#include <stdint.h>

#define S_LEN   2048
#define D_MODEL 1024
#define NH      16
#define DH      64
#define BATCH   2
#define M_ROWS  (BATCH * S_LEN)   // 4096

// ---------------------------------------------------------------------------
// Scratch (device globals: allocation-free, graph-capture safe)
// ---------------------------------------------------------------------------
__device__ __half g_qh[M_ROWS * D_MODEL];
__device__ __half g_kh[M_ROWS * D_MODEL];
__device__ __half g_vh[M_ROWS * D_MODEL];
__device__ __half g_atth[M_ROWS * D_MODEL];
__device__ __half g_xh[M_ROWS * D_MODEL];
__device__ __half g_wh[4][D_MODEL * D_MODEL];

// ---------------------------------------------------------------------------
// Helpers
// ---------------------------------------------------------------------------
__device__ __forceinline__ void mma_f16(float* c, const uint32_t* a,
                                        const uint32_t* b) {
    asm volatile(
        "mma.sync.aligned.m16n8k16.row.col.f32.f16.f16.f32 "
        "{%0,%1,%2,%3}, {%4,%5,%6,%7}, {%8,%9}, {%0,%1,%2,%3};\n"
        : "+f"(c[0]), "+f"(c[1]), "+f"(c[2]), "+f"(c[3])
        : "r"(a[0]), "r"(a[1]), "r"(a[2]), "r"(a[3]),
          "r"(b[0]), "r"(b[1]));
}

#define LDSM_X4(r0, r1, r2, r3, addr) \
    asm volatile("ldmatrix.sync.aligned.m8n8.x4.shared.b16 {%0,%1,%2,%3}, [%4];" \
                 : "=r"(r0), "=r"(r1), "=r"(r2), "=r"(r3) : "r"(addr))

#define LDSM_X4_T(r0, r1, r2, r3, addr) \
    asm volatile("ldmatrix.sync.aligned.m8n8.x4.trans.shared.b16 {%0,%1,%2,%3}, [%4];" \
                 : "=r"(r0), "=r"(r1), "=r"(r2), "=r"(r3) : "r"(addr))

#define LDSM_X2_T(r0, r1, addr) \
    asm volatile("ldmatrix.sync.aligned.m8n8.x2.trans.shared.b16 {%0,%1}, [%2];" \
                 : "=r"(r0), "=r"(r1) : "r"(addr))

__device__ __forceinline__ uint32_t smemu32(const void* p) {
    return (uint32_t)__cvta_generic_to_shared(p);
}

// Pack two fp32 into fp16x2 (RNE), lo = a, hi = b
__device__ __forceinline__ uint32_t pack_h2(float a, float b) {
    uint32_t r;
    asm("cvt.rn.f16x2.f32 %0, %1, %2;" : "=r"(r) : "f"(b), "f"(a));
    return r;
}

// exp2 approximations (MUFU)
__device__ __forceinline__ uint32_t hex2(uint32_t x) {
    uint32_t r;
    asm("ex2.approx.f16x2 %0, %1;" : "=r"(r) : "r"(x));
    return r;
}
__device__ __forceinline__ float fex2(float x) {
    float r;
    asm("ex2.approx.f32 %0, %1;" : "=f"(r) : "f"(x));
    return r;
}

#define CP_ASYNC16(dst, src) \
    asm volatile("cp.async.cg.shared.global [%0], [%1], 16;\n" \
                 :: "r"(dst), "l"(src))
#define CP_COMMIT() asm volatile("cp.async.commit_group;\n" ::: "memory")

// ---------------------------------------------------------------------------
// Fused fp32 -> fp16 prep: grid.y selects tensor (0=X, 1..4=W)
// ---------------------------------------------------------------------------
#define NX8 (M_ROWS * D_MODEL / 8)
#define NW8 (D_MODEL * D_MODEL / 8)

__global__ void f2h5_kernel(const float* __restrict__ x,
                            const float* __restrict__ wq,
                            const float* __restrict__ wk,
                            const float* __restrict__ wv,
                            const float* __restrict__ wo,
                            __half* __restrict__ xh,
                            __half* __restrict__ wh)
{
    const int z = blockIdx.y;
    const int i = blockIdx.x * blockDim.x + threadIdx.x;
    const float* src;
    __half* dst;
    int n8;
    if (z == 0) { src = x; dst = xh; n8 = NX8; }
    else {
        src = (z == 1) ? wq : (z == 2) ? wk : (z == 3) ? wv : wo;
        dst = wh + (size_t)(z - 1) * D_MODEL * D_MODEL;
        n8 = NW8;
    }
    if (i < n8) {
        float4 v0 = ((const float4*)src)[i * 2];
        float4 v1 = ((const float4*)src)[i * 2 + 1];
        uint4 u;
        u.x = pack_h2(v0.x, v0.y);
        u.y = pack_h2(v0.z, v0.w);
        u.z = pack_h2(v1.x, v1.y);
        u.w = pack_h2(v1.z, v1.w);
        ((uint4*)dst)[i] = u;
    }
}

// ---------------------------------------------------------------------------
// FP16 tensor-core GEMM: Y[M,N] = X[M,K] @ W[N,K]^T  (fp32 accumulate)
// R13 tile config: BM=BN=128, BK=32, 256 threads (8 warps, 2x4), warp tile
// 64x32; 3-stage cp.async ring, one sync/iter.
// NEW: __launch_bounds__(256, 2) raises reg budget to 128 (true residency);
// both k16-steps' fragments hoisted before the mmas so ldsm(ks=1) overlaps
// mma(ks=0) at register level.
// ---------------------------------------------------------------------------
#define HST 20                        // smem row stride in 4B words
#define HSTAGE_W (128 * HST)          // words per operand per stage
#define HSMEM_BYTES (6 * HSTAGE_W * 4)   // 3 stages x 2 operands = 61440 B

template <typename OT>
__global__ __launch_bounds__(256, 2) void gemm_h(
    const __half* __restrict__ X,
    const __half* __restrict__ W0, const __half* __restrict__ W1,
    const __half* __restrict__ W2,
    OT* __restrict__ Y0, OT* __restrict__ Y1, OT* __restrict__ Y2,
    int M, int N, int K)
{
    extern __shared__ __align__(16) uint32_t gsm[];

    const int z = blockIdx.z;
    const __half* W = (z == 0) ? W0 : (z == 1) ? W1 : W2;
    OT*           Y = (z == 0) ? Y0 : (z == 1) ? Y1 : Y2;

    const int tid  = threadIdx.x;
    const int lane = tid & 31;
    const int warp = tid >> 5;
    const int wm   = warp >> 2;       // 0..1
    const int wn   = warp & 3;        // 0..3
    const int grp  = lane >> 2;       // 0..7
    const int t4   = lane & 3;        // 0..3

    const int row0 = blockIdx.y * 128;
    const int col0 = blockIdx.x * 128;

    // cp.async mapping: thread covers one 16-half chunk per operand
    const int lr = tid >> 1;          // 0..127
    const int lh = (tid & 1) * 16;    // 0 or 16 halfs
    const __half* Xg = X + (size_t)(row0 + lr) * K + lh;
    const __half* Wg = W + (size_t)(col0 + lr) * K + lh;
    const uint32_t sbase = smemu32(gsm);
    const uint32_t doff  = (uint32_t)(lr * HST + (tid & 1) * 8) * 4u;

    auto issue_stage = [&](int it) {
        const int s  = it % 3;
        const int k0 = it * 32;
        uint32_t xd = sbase + (uint32_t)(s * 2)     * HSTAGE_W * 4u + doff;
        uint32_t wd = sbase + (uint32_t)(s * 2 + 1) * HSTAGE_W * 4u + doff;
        CP_ASYNC16(xd,      Xg + k0);
        CP_ASYNC16(xd + 16, Xg + k0 + 8);
        CP_ASYNC16(wd,      Wg + k0);
        CP_ASYNC16(wd + 16, Wg + k0 + 8);
        CP_COMMIT();
    };

    // ldmatrix lane offsets (bytes)
    const uint32_t aoff = (uint32_t)((wm * 64 + (lane & 15)) * HST * 4
                                     + ((lane >> 4) & 1) * 16);
    const uint32_t boff = (uint32_t)((wn * 32 + (lane & 7) + ((lane >> 4) << 3))
                                     * HST * 4 + ((lane >> 3) & 1) * 16);

    float acc[4][4][4] = {};

    const int niter = K / 32;         // 32
    issue_stage(0);
    issue_stage(1);

    for (int it = 0; it < niter; it++) {
        if (it + 1 < niter)
            asm volatile("cp.async.wait_group 1;" ::: "memory");
        else
            asm volatile("cp.async.wait_group 0;" ::: "memory");
        __syncthreads();
        if (it + 2 < niter) issue_stage(it + 2);   // safe: 3-stage ring

        const uint32_t xsb = sbase + (uint32_t)((it % 3) * 2) * HSTAGE_W * 4u;
        const uint32_t wsb = xsb + HSTAGE_W * 4u;

        // Hoist BOTH k16-steps' fragments (48 regs) before the 32 mmas:
        // ldsm of ks=1 overlaps mma of ks=0 at the register level.
        uint32_t a[2][4][4], b[2][2][4];
        #pragma unroll
        for (int ks = 0; ks < 2; ks++) {
            const uint32_t kb = ks * 32;   // 8 words = 16 halfs
            #pragma unroll
            for (int am = 0; am < 4; am++)
                LDSM_X4(a[ks][am][0], a[ks][am][1], a[ks][am][2], a[ks][am][3],
                        xsb + aoff + (uint32_t)(am * 16 * HST * 4) + kb);
            #pragma unroll
            for (int bp = 0; bp < 2; bp++)
                LDSM_X4(b[ks][bp][0], b[ks][bp][1], b[ks][bp][2], b[ks][bp][3],
                        wsb + boff + (uint32_t)(bp * 16 * HST * 4) + kb);
        }
        #pragma unroll
        for (int ks = 0; ks < 2; ks++)
            #pragma unroll
            for (int am = 0; am < 4; am++)
                #pragma unroll
                for (int bn = 0; bn < 4; bn++)
                    mma_f16(acc[am][bn], a[ks][am], &b[ks][bn >> 1][(bn & 1) * 2]);
    }

    #pragma unroll
    for (int am = 0; am < 4; am++) {
        const int r = row0 + wm * 64 + am * 16 + grp;
        #pragma unroll
        for (int bn = 0; bn < 4; bn++) {
            const int c = col0 + wn * 32 + bn * 8 + t4 * 2;
            if (sizeof(OT) == 4) {
                *(float2*)((float*)Y + (size_t)r * N + c) =
                    make_float2(acc[am][bn][0], acc[am][bn][1]);
                *(float2*)((float*)Y + (size_t)(r + 8) * N + c) =
                    make_float2(acc[am][bn][2], acc[am][bn][3]);
            } else {
                *(uint32_t*)((__half*)Y + (size_t)r * N + c) =
                    pack_h2(acc[am][bn][0], acc[am][bn][1]);
                *(uint32_t*)((__half*)Y + (size_t)(r + 8) * N + c) =
                    pack_h2(acc[am][bn][2], acc[am][bn][3]);
            }
        }
    }
}

// ---------------------------------------------------------------------------
// FP16 flash attention (causal), log2-domain softmax, l via tensor core
// (R13 config, proven 280.6us total). __launch_bounds__(256, 2) declares the
// true smem-limited residency so ptxas can use up to 128 regs for scheduling.
// BQ=128, BKV=64, 256 threads (8 warps); warp w owns q-rows [16w, 16w+16).
// ---------------------------------------------------------------------------
#define FST 36   // word stride (ldmatrix conflict-free: banks 4r)
#define KVSTAGE_W (128 * FST)                    // K 64 rows + V 64 rows
#define ATTN_SMEM_BYTES ((128 * FST + 3 * KVSTAGE_W) * 4)   // 73728 B
#define SCALE_L2E 0.1803368801111244f            // 0.125 * log2(e)

__global__ __launch_bounds__(256, 2) void attn_h(
    const __half* __restrict__ Qg, const __half* __restrict__ Kg,
    const __half* __restrict__ Vg, __half* __restrict__ Og)
{
    extern __shared__ __align__(16) uint32_t sm[];
    uint32_t* Qs = sm;                  // [128][32w] (i, d)

    const int tid  = threadIdx.x;
    const int lane = tid & 31;
    const int warp = tid >> 5;
    const int grp  = lane >> 2;         // 0..7
    const int t4   = lane & 3;          // 0..3
    const int m0   = warp * 16;

    const int qt = (gridDim.x - 1) - blockIdx.x;   // heavy tiles first
    const int q0 = qt * 128;
    const int h  = blockIdx.y;
    const int b  = blockIdx.z;

    const __half* Qb = Qg + ((size_t)b * S_LEN + q0) * D_MODEL + h * DH;
    const __half* Kb = Kg + (size_t)b * S_LEN * D_MODEL + h * DH;
    const __half* Vb = Vg + (size_t)b * S_LEN * D_MODEL + h * DH;

    const uint32_t sQ  = smemu32(Qs);
    const uint32_t sKV = sQ + 128 * FST * 4;

    // ldmatrix lane offsets (bytes)
    const uint32_t aoff = (uint32_t)((lane & 15) * FST * 4
                                     + ((lane >> 4) & 1) * 16);
    const uint32_t boff = (uint32_t)(((lane & 7) + ((lane >> 4) << 3)) * FST * 4
                                     + ((lane >> 3) & 1) * 16);
    // trans B-operand offsets for V (rows = j, 16B col select by lane>>4)
    const uint32_t voff = (uint32_t)((lane & 15) * FST * 4
                                     + ((lane >> 4) & 1) * 16);
    // ones-column (col 64) B-operand offset: 16 rows, bytes 128..143
    const uint32_t loff = (uint32_t)((lane & 15) * FST * 4 + 128);

    // cp.async mapping for K/V tiles: 2 chunks each per thread
    const int krow = tid >> 3;          // 0..31 base (2 rounds -> 64 rows)
    const int kch  = tid & 7;           // 16B chunk in row

    auto issue_kv = [&](int kt) {
        const int s  = kt % 3;
        const int k0 = kt * 64;
        const uint32_t base = sKV + (uint32_t)s * KVSTAGE_W * 4u;
        #pragma unroll
        for (int r = 0; r < 2; r++) {
            const int row = krow + r * 32;
            const uint32_t d = base + (uint32_t)(row * FST * 4 + kch * 16);
            CP_ASYNC16(d, Kb + (size_t)(k0 + row) * D_MODEL + kch * 8);
            CP_ASYNC16(d + (uint32_t)(64 * FST * 4),
                       Vb + (size_t)(k0 + row) * D_MODEL + kch * 8);
        }
        CP_COMMIT();
    };

    issue_kv(0);

    // Init ones-column words (32..35) of every V row, all 3 ring stages.
    // cp.async never touches these words; the in-loop __syncthreads covers
    // visibility before first use.
    for (int i = tid; i < 3 * 64; i += 256) {
        const int st = i >> 6, row = i & 63;
        uint32_t* p = sm + 128 * FST + st * KVSTAGE_W + 64 * FST + row * FST + 32;
        p[0] = 0x00003C00u;   // col 64 = 1.0h, col 65 = 0
        p[1] = 0; p[2] = 0; p[3] = 0;
    }

    // Load Q tile (128 x 64 halfs)
    #pragma unroll
    for (int r = 0; r < 4; r++) {
        int idx = tid + r * 256;
        int row = idx >> 3;             // 0..127
        int ch  = idx & 7;              // 8 halfs each
        uint4 v = *(const uint4*)(Qb + (size_t)row * D_MODEL + ch * 8);
        *(uint4*)(Qs + row * FST + ch * 4) = v;
    }

    float mr[2] = {-INFINITY, -INFINITY};
    float o[8][4];
    float l_acc[4] = {0.f, 0.f, 0.f, 0.f};
    #pragma unroll
    for (int n = 0; n < 8; n++)
        #pragma unroll
        for (int r = 0; r < 4; r++) o[n][r] = 0.f;

    const int ntiles = 2 * qt + 2;
    if (ntiles > 1) issue_kv(1);

    for (int kt = 0; kt < ntiles; kt++) {
        if (kt + 1 < ntiles)
            asm volatile("cp.async.wait_group 1;" ::: "memory");
        else
            asm volatile("cp.async.wait_group 0;" ::: "memory");
        __syncthreads();
        if (kt + 2 < ntiles) issue_kv(kt + 2);   // safe: 3-stage ring

        const int k0 = kt * 64;
        const uint32_t sKst = sKV + (uint32_t)((kt % 3)) * KVSTAGE_W * 4u;
        const uint32_t sVst = sKst + (uint32_t)(64 * FST * 4);

        const bool active = (k0 <= q0 + m0 + 15);
        if (active) {
            // ---- S = Q K^T ----
            float s[8][4];
            #pragma unroll
            for (int n = 0; n < 8; n++)
                #pragma unroll
                for (int r = 0; r < 4; r++) s[n][r] = 0.f;

            #pragma unroll
            for (int ks = 0; ks < 4; ks++) {
                const uint32_t kb = ks * 32;
                uint32_t a[4], bk[4][4];
                LDSM_X4(a[0], a[1], a[2], a[3],
                        sQ + (uint32_t)(m0 * FST * 4) + aoff + kb);
                #pragma unroll
                for (int np = 0; np < 4; np++)
                    LDSM_X4(bk[np][0], bk[np][1], bk[np][2], bk[np][3],
                            sKst + boff + (uint32_t)(np * 16 * FST * 4) + kb);
                #pragma unroll
                for (int n = 0; n < 8; n++)
                    mma_f16(s[n], a, &bk[n >> 1][(n & 1) * 2]);
            }
            // scale into log2 domain: s * 0.125 * log2(e)
            #pragma unroll
            for (int n = 0; n < 8; n++) {
                s[n][0] *= SCALE_L2E; s[n][1] *= SCALE_L2E;
                s[n][2] *= SCALE_L2E; s[n][3] *= SCALE_L2E;
            }

            // ---- causal mask (only when tile clips this warp's rows) ----
            if (k0 + 63 > q0 + m0) {
                const int i0 = q0 + m0 + grp, i1 = i0 + 8;
                #pragma unroll
                for (int n = 0; n < 8; n++) {
                    const int j0 = k0 + n * 8 + t4 * 2;
                    if (j0     > i0) s[n][0] = -INFINITY;
                    if (j0 + 1 > i0) s[n][1] = -INFINITY;
                    if (j0     > i1) s[n][2] = -INFINITY;
                    if (j0 + 1 > i1) s[n][3] = -INFINITY;
                }
            }

            // ---- online softmax max (rows grp, grp+8; quad shuffles) ----
            float ml0 = -INFINITY, ml1 = -INFINITY;
            #pragma unroll
            for (int n = 0; n < 8; n++) {
                ml0 = fmaxf(ml0, fmaxf(s[n][0], s[n][1]));
                ml1 = fmaxf(ml1, fmaxf(s[n][2], s[n][3]));
            }
            ml0 = fmaxf(ml0, __shfl_xor_sync(0xffffffffu, ml0, 1));
            ml0 = fmaxf(ml0, __shfl_xor_sync(0xffffffffu, ml0, 2));
            ml1 = fmaxf(ml1, __shfl_xor_sync(0xffffffffu, ml1, 1));
            ml1 = fmaxf(ml1, __shfl_xor_sync(0xffffffffu, ml1, 2));

            const float mn0 = fmaxf(mr[0], ml0);
            const float mn1 = fmaxf(mr[1], ml1);
            const float al0 = fex2(mr[0] - mn0);
            const float al1 = fex2(mr[1] - mn1);
            mr[0] = mn0; mr[1] = mn1;

            // ---- P = exp2(s - m) directly in fp16x2 (A-fragment layout) ----
            uint32_t p2[8][2];
            #pragma unroll
            for (int n = 0; n < 8; n++) {
                p2[n][0] = hex2(pack_h2(s[n][0] - mn0, s[n][1] - mn0));
                p2[n][1] = hex2(pack_h2(s[n][2] - mn1, s[n][3] - mn1));
            }

            // rescale O and l by alpha
            #pragma unroll
            for (int n = 0; n < 8; n++) {
                o[n][0] *= al0; o[n][1] *= al0;
                o[n][2] *= al1; o[n][3] *= al1;
            }
            l_acc[0] *= al0; l_acc[1] *= al0;
            l_acc[2] *= al1; l_acc[3] *= al1;

            // ---- O += P V, l += P 1 (ones column) ----
            #pragma unroll
            for (int ks = 0; ks < 4; ks++) {
                uint32_t ap[4], bv[4][4], bl[2];
                ap[0] = p2[2 * ks][0];
                ap[1] = p2[2 * ks][1];
                ap[2] = p2[2 * ks + 1][0];
                ap[3] = p2[2 * ks + 1][1];
                const uint32_t vrow = sVst + (uint32_t)(ks * 16 * FST * 4);
                #pragma unroll
                for (int np = 0; np < 4; np++)
                    LDSM_X4_T(bv[np][0], bv[np][1], bv[np][2], bv[np][3],
                              vrow + voff + (uint32_t)(np * 32));
                LDSM_X2_T(bl[0], bl[1], vrow + loff);
                #pragma unroll
                for (int n = 0; n < 8; n++)
                    mma_f16(o[n], ap, &bv[n >> 1][(n & 1) * 2]);
                mma_f16(l_acc, ap, bl);
            }
        }
    }

    // ---- broadcast row sums (col 0 of l fragment lives at t4==0) ----
    const float l0 = __shfl_sync(0xffffffffu, l_acc[0], lane & ~3);
    const float l1 = __shfl_sync(0xffffffffu, l_acc[2], lane & ~3);
    const float inv0 = 1.f / l0;
    const float inv1 = 1.f / l1;

    __half* Ob = Og + ((size_t)b * S_LEN + q0 + m0) * D_MODEL + h * DH;
    #pragma unroll
    for (int n = 0; n < 8; n++) {
        const int c = n * 8 + t4 * 2;
        *(uint32_t*)(Ob + (size_t)grp * D_MODEL + c) =
            pack_h2(o[n][0] * inv0, o[n][1] * inv0);
        *(uint32_t*)(Ob + (size_t)(grp + 8) * D_MODEL + c) =
            pack_h2(o[n][2] * inv1, o[n][3] * inv1);
    }
}

// ---------------------------------------------------------------------------
// Launch
// ---------------------------------------------------------------------------
extern "C" void kernel_launch(void* const* d_in, const int* in_sizes, int n_in,
                              void* d_out, int out_size)
{
    const float* x  = (const float*)d_in[0];
    const float* Wq = (const float*)d_in[1];
    const float* Wk = (const float*)d_in[2];
    const float* Wv = (const float*)d_in[3];
    const float* Wo = (const float*)d_in[4];
    float* out = (float*)d_out;

    __half *q, *k, *v, *att, *xh, *wh;
    cudaGetSymbolAddress((void**)&q,   g_qh);
    cudaGetSymbolAddress((void**)&k,   g_kh);
    cudaGetSymbolAddress((void**)&v,   g_vh);
    cudaGetSymbolAddress((void**)&att, g_atth);
    cudaGetSymbolAddress((void**)&xh,  g_xh);
    cudaGetSymbolAddress((void**)&wh,  g_wh);
    __half* wq = wh;
    __half* wk = wh + 1 * (size_t)D_MODEL * D_MODEL;
    __half* wv = wh + 2 * (size_t)D_MODEL * D_MODEL;
    __half* wo = wh + 3 * (size_t)D_MODEL * D_MODEL;

    cudaFuncSetAttribute(gemm_h<__half>,
                         cudaFuncAttributeMaxDynamicSharedMemorySize, HSMEM_BYTES);
    cudaFuncSetAttribute(gemm_h<float>,
                         cudaFuncAttributeMaxDynamicSharedMemorySize, HSMEM_BYTES);
    cudaFuncSetAttribute(attn_h,
                         cudaFuncAttributeMaxDynamicSharedMemorySize, ATTN_SMEM_BYTES);

    // fp32 -> fp16 prep, one launch (grid.y selects tensor)
    f2h5_kernel<<<dim3(NX8 / 256, 5), 256>>>(x, Wq, Wk, Wv, Wo, xh, wh);

    // Fused QKV projections (fp16 out)
    dim3 gq(D_MODEL / 128, M_ROWS / 128, 3);   // (8, 32, 3)
    gemm_h<__half><<<gq, 256, HSMEM_BYTES>>>(xh, wq, wk, wv, q, k, v,
                                             M_ROWS, D_MODEL, D_MODEL);

    attn_h<<<dim3(S_LEN / 128, NH, BATCH), 256, ATTN_SMEM_BYTES>>>(q, k, v, att);

    // O projection (fp32 out to d_out)
    dim3 go(D_MODEL / 128, M_ROWS / 128, 1);
    gemm_h<float><<<go, 256, HSMEM_BYTES>>>(att, wo, wo, wo, out, out, out,
                                            M_ROWS, D_MODEL, D_MODEL);
}